// round 13
// baseline (speedup 1.0000x reference)
#include <cuda_runtime.h>
#include <math.h>

// Shapes (fixed):
//   x  : [B=8, C=128, D=4, H=128, W=128] -> 67,108,864 fp32 (256 MB)
//   w1, w2 : [C, C] row-major (w[o,c] = w[o*128 + c]); b1, b2 : [C]
// out = x * sigmoid(W2 @ relu(W1 @ max_{dhw}(x) + b1) + b2), gate per (b,c).

#define BC 1024              // B*C slices
#define SLICE4 16384         // 65536 floats / 4 per (b,c)

__device__ float d_gp2[2 * BC];  // per-(b,c) half-slice partial maxima
__device__ float d_gate[BC];     // per-(b,c) sigmoid gate

// ---------------- Kernel 1: half-slice max reduce (grid=2048) ----------------
// Block blk covers half (blk&1) of slice (blk>>1): 256 threads x 32 float4.
__global__ __launch_bounds__(256) void max_reduce_kernel(const float4* __restrict__ x4) {
    const int blk = blockIdx.x;
    const float4* base = x4 + (size_t)blk * (SLICE4 / 2);
    const int t = threadIdx.x;

    float m0 = -INFINITY, m1 = -INFINITY, m2 = -INFINITY, m3 = -INFINITY;
    #pragma unroll
    for (int i = 0; i < 8; i++) {
        float4 a = base[t + (4 * i + 0) * 256];
        float4 b = base[t + (4 * i + 1) * 256];
        float4 c = base[t + (4 * i + 2) * 256];
        float4 d = base[t + (4 * i + 3) * 256];
        m0 = fmaxf(m0, fmaxf(fmaxf(a.x, a.y), fmaxf(a.z, a.w)));
        m1 = fmaxf(m1, fmaxf(fmaxf(b.x, b.y), fmaxf(b.z, b.w)));
        m2 = fmaxf(m2, fmaxf(fmaxf(c.x, c.y), fmaxf(c.z, c.w)));
        m3 = fmaxf(m3, fmaxf(fmaxf(d.x, d.y), fmaxf(d.z, d.w)));
    }
    float m = fmaxf(fmaxf(m0, m1), fmaxf(m2, m3));

    #pragma unroll
    for (int off = 16; off > 0; off >>= 1)
        m = fmaxf(m, __shfl_xor_sync(0xFFFFFFFFu, m, off));

    __shared__ float s[8];
    if ((t & 31) == 0) s[t >> 5] = m;
    __syncthreads();
    if (t == 0) {
        float r = s[0];
        #pragma unroll
        for (int w = 1; w < 8; w++) r = fmaxf(r, s[w]);
        d_gp2[blk] = r;
    }
}

// ---------------- Kernel 2: lean MLP gate ----------------
// Grid=8 (one block per batch), 256 threads = 8 warps.
// Warp w handles output channels c = w*16..w*16+15. For each channel, ONE
// coalesced float4-per-lane load covers the whole 128-float weight row;
// dot against s_gp (float4 per lane) + shuffle reduce. No smem weight staging.
__global__ __launch_bounds__(256) void mlp_gate_kernel(const float* __restrict__ w1,
                                                       const float* __restrict__ b1,
                                                       const float* __restrict__ w2,
                                                       const float* __restrict__ b2) {
    __shared__ float s_gp[128];
    __shared__ float s_h[128];
    const int b = blockIdx.x;
    const int t = threadIdx.x;
    const int wid = t >> 5, lane = t & 31;

    if (t < 128) {
        const int bc = b * 128 + t;
        s_gp[t] = fmaxf(d_gp2[2 * bc], d_gp2[2 * bc + 1]);
    }
    __syncthreads();

    // layer 1
    {
        float4 gv = ((const float4*)s_gp)[lane];
        #pragma unroll
        for (int k = 0; k < 16; k++) {
            const int c = wid * 16 + k;
            float4 wv = ((const float4*)(w1 + c * 128))[lane];
            float p = fmaf(gv.x, wv.x, fmaf(gv.y, wv.y, fmaf(gv.z, wv.z, gv.w * wv.w)));
            #pragma unroll
            for (int off = 16; off > 0; off >>= 1)
                p += __shfl_xor_sync(0xFFFFFFFFu, p, off);
            if (lane == 0) s_h[c] = fmaxf(p + b1[c], 0.0f);
        }
    }
    __syncthreads();

    // layer 2
    {
        float4 hv = ((const float4*)s_h)[lane];
        #pragma unroll
        for (int k = 0; k < 16; k++) {
            const int c = wid * 16 + k;
            float4 wv = ((const float4*)(w2 + c * 128))[lane];
            float p = fmaf(hv.x, wv.x, fmaf(hv.y, wv.y, fmaf(hv.z, wv.z, hv.w * wv.w)));
            #pragma unroll
            for (int off = 16; off > 0; off >>= 1)
                p += __shfl_xor_sync(0xFFFFFFFFu, p, off);
            if (lane == 0) {
                float z = p + b2[c];
                d_gate[b * 128 + c] = 1.0f / (1.0f + __expf(-z));
            }
        }
    }
}

// ---------------- Kernel 3: broadcast scale (grid=2048, reverse) ----------------
// Measured-best config: 2 blocks per slice, reverse order, default loads,
// evict-first stores. 77.7us @ 78.5% DRAM in R9.
__global__ __launch_bounds__(256) void scale_kernel(const float4* __restrict__ x4,
                                                    float4* __restrict__ o4) {
    const int blk = (2 * BC - 1) - blockIdx.x;
    const int bc = blk >> 1;
    const float g = d_gate[bc];
    const size_t off = (size_t)blk * (SLICE4 / 2);
    const float4* src = x4 + off;
    float4* dst = o4 + off;
    const int t = threadIdx.x;

    #pragma unroll
    for (int i = 0; i < 32; i++) {
        float4 v = src[t + i * 256];
        v.x *= g; v.y *= g; v.z *= g; v.w *= g;
        __stcs(dst + t + i * 256, v);
    }
}

extern "C" void kernel_launch(void* const* d_in, const int* in_sizes, int n_in,
                              void* d_out, int out_size) {
    const float* x  = (const float*)d_in[0];
    const float* w1 = (const float*)d_in[1];
    const float* b1 = (const float*)d_in[2];
    const float* w2 = (const float*)d_in[3];
    const float* b2 = (const float*)d_in[4];
    float* out = (float*)d_out;

    max_reduce_kernel<<<2 * BC, 256>>>((const float4*)x);
    mlp_gate_kernel<<<8, 256>>>(w1, b1, w2, b2);
    scale_kernel<<<2 * BC, 256>>>((const float4*)x, (float4*)out);
}